// round 13
// baseline (speedup 1.0000x reference)
#include <cuda_runtime.h>
#include <cuda_fp16.h>
#include <mma.h>
#include <cstddef>
#include <cstdint>

using namespace nvcuda;

// Problem dims (fixed by the dataset)
#define B_   256
#define L_   64
#define DI_  2048
#define T_   32
#define DT_  512
#define U_   512
#define A_   512
#define U3_  1536
#define HN_  2048   // combined h-GEMM output: hproj(512) | mi(1536)
#define NF_  2048   // fused img GEMM width: imgproj(512) | imgk(1536)

// ---------------- device scratch (static, allocation-free) ----------------
__device__ __half g_img16  [(size_t)B_*L_*DI_];     // fp16 img [M,K] row-major
__device__ __half g_text16 [(size_t)B_*T_*DT_];
__device__ __half g_Wbig   [(size_t)DI_*NF_];       // [wimg | wctx]  [K=2048, N=2048] row-major
__device__ __half g_Wtext  [(size_t)DT_*U3_];       // kernel[:512]   [K=512,  N=1536] row-major
__device__ float  g_bias2048[NF_];                  // [att_img_bias | 0]
__device__ __half g_Wh16   [U_*HN_];                // [att_hidden | recurrent] row-major
__device__ float  g_hbias  [HN_];
__device__ __half g_imgpk  [(size_t)B_*L_*NF_];     // fused: imgproj | imgk
__device__ float  g_mxtext [(size_t)B_*T_*U3_];     // text @ kernel[:512] + bias
__device__ float  g_hmi    [B_*HN_];                // per-step h-GEMM out
__device__ float  g_h      [B_*U_];
__device__ __half g_h16    [B_*U_];
__device__ unsigned g_barcnt;

// ---------------- small helpers ----------------
__device__ __forceinline__ float tanh_fast(float x) {
    float y; asm("tanh.approx.f32 %0, %1;" : "=f"(y) : "f"(x)); return y;
}
__device__ __forceinline__ void cp_async16(void* sm, const void* gm) {
    unsigned s = (unsigned)__cvta_generic_to_shared(sm);
    asm volatile("cp.async.cg.shared.global [%0], [%1], 16;\n" :: "r"(s), "l"(gm));
}
__device__ __forceinline__ void cp_commit() { asm volatile("cp.async.commit_group;\n"); }
__device__ __forceinline__ void cp_wait0()  { asm volatile("cp.async.wait_group 0;\n"); }

// software grid barrier (all CTAs resident by construction)
__device__ __forceinline__ void grid_sync(unsigned target) {
    __syncthreads();
    if (threadIdx.x == 0) {
        asm volatile("fence.acq_rel.gpu;" ::: "memory");
        asm volatile("red.relaxed.gpu.add.u32 [%0], 1;" :: "l"(&g_barcnt) : "memory");
        unsigned v;
        do {
            asm volatile("ld.acquire.gpu.u32 %0, [%1];" : "=r"(v) : "l"(&g_barcnt) : "memory");
            if (v < target) __nanosleep(32);
        } while (v < target);
    }
    __syncthreads();
}

// ---------------- setup kernels ----------------
// vectorized fp32 -> fp16
__global__ void cvt_f32_f16_v8(const float* __restrict__ s, __half* __restrict__ d, size_t n8) {
    size_t i = (size_t)blockIdx.x * blockDim.x + threadIdx.x;
    if (i >= n8) return;
    const float4* s4 = reinterpret_cast<const float4*>(s) + i * 2;
    float4 a = s4[0], b = s4[1];
    __half2 h[4];
    h[0] = __floats2half2_rn(a.x, a.y);
    h[1] = __floats2half2_rn(a.z, a.w);
    h[2] = __floats2half2_rn(b.x, b.y);
    h[3] = __floats2half2_rn(b.z, b.w);
    reinterpret_cast<uint4*>(d)[i] = *reinterpret_cast<uint4*>(h);
}

// copy+cvt the three K-major weight slabs (sources already [K,N] row-major)
__global__ void copy_weights(const float* __restrict__ wimg, const float* __restrict__ kernel) {
    const int job = blockIdx.y;
    const float* src; __half* dst;
    int rows, cols, dst_ld, n0out;
    if (job == 0)      { src = wimg;                       rows = DI_; cols = 512;  dst = g_Wbig;  dst_ld = NF_; n0out = 0;   }
    else if (job == 1) { src = kernel + (size_t)DT_ * U3_; rows = DI_; cols = U3_;  dst = g_Wbig;  dst_ld = NF_; n0out = 512; }
    else               { src = kernel;                     rows = DT_; cols = U3_;  dst = g_Wtext; dst_ld = U3_; n0out = 0;   }
    const int cols8 = cols / 8;
    const int total = rows * cols8;
    for (int i8 = blockIdx.x * blockDim.x + threadIdx.x; i8 < total;
         i8 += gridDim.x * blockDim.x) {
        int r = i8 / cols8, c = (i8 % cols8) * 8;
        const float* sp = src + (size_t)r * cols + c;
        float4 a = reinterpret_cast<const float4*>(sp)[0];
        float4 b = reinterpret_cast<const float4*>(sp)[1];
        __half2 h[4];
        h[0] = __floats2half2_rn(a.x, a.y);
        h[1] = __floats2half2_rn(a.z, a.w);
        h[2] = __floats2half2_rn(b.x, b.y);
        h[3] = __floats2half2_rn(b.z, b.w);
        *reinterpret_cast<uint4*>(dst + (size_t)r * dst_ld + n0out + c) =
            *reinterpret_cast<uint4*>(h);
    }
}

// Wh = [att_hidden | recurrent] fp16 row-major
__global__ void build_Wh_v8(const float* __restrict__ attk, const float* __restrict__ reck) {
    int i8 = blockIdx.x * blockDim.x + threadIdx.x;     // U_*HN_/8
    if (i8 >= U_ * HN_ / 8) return;
    int k = i8 >> 8, c = (i8 & 255) * 8;
    const float* src = (c < 512) ? (attk + (size_t)k * 512 + c)
                                 : (reck + (size_t)k * U3_ + (c - 512));
    float4 a = reinterpret_cast<const float4*>(src)[0];
    float4 b = reinterpret_cast<const float4*>(src)[1];
    __half2 h[4];
    h[0] = __floats2half2_rn(a.x, a.y);
    h[1] = __floats2half2_rn(a.z, a.w);
    h[2] = __floats2half2_rn(b.x, b.y);
    h[3] = __floats2half2_rn(b.z, b.w);
    reinterpret_cast<uint4*>(g_Wh16)[i8] = *reinterpret_cast<uint4*>(h);
}

// biases + h init + barrier reset
__global__ void build_misc(const float* __restrict__ bimg,
                           const float* __restrict__ attb, const float* __restrict__ recb) {
    int i = blockIdx.x * blockDim.x + threadIdx.x;
    if (i == 0) g_barcnt = 0;
    if (i < NF_) g_bias2048[i] = (i < 512) ? bimg[i] : 0.f;
    if (i < HN_) g_hbias[i]    = (i < 512) ? attb[i] : recb[i - 512];
    if (i < B_ * U_) { g_h[i] = 0.f; g_h16[i] = __float2half(0.f); }
}

// ---------------- cp.async double-buffered WMMA GEMM (BK=64) ---------------
// C[M,N] = A[M,K] @ B[K,N] (+bias via accumulator init), out fp32 or fp16.
// 256 threads = 8 warps; 128x128x64 tiles, dynamic smem (2 stages, 71.7 KB),
// __launch_bounds__(256,2) -> 2 CTAs/SM (143 KB smem).
template<int BM, int BN, int BK, int WM, int WN, bool OUT_HALF>
__global__ __launch_bounds__(256, 2)
void gemm_pipe(const __half* __restrict__ A, const __half* __restrict__ Bm,
               const float* __restrict__ bias, float* __restrict__ Cf,
               __half* __restrict__ Ch, int M, int N, int K)
{
    constexpr int WARPS_M = BM / WM, WARPS_N = BN / WN;
    static_assert(WARPS_M * WARPS_N == 8, "8 warps");
    constexpr int FM = WM / 16, FN = WN / 16;
    constexpr int ASTR = BK + 8, BSTR = BN + 8;          // half strides (16B-mult rows)
    constexpr int ABYTES = BM * ASTR * 2, BBYTES = BK * BSTR * 2;
    extern __shared__ __align__(16) char smem[];

    const int tid = threadIdx.x, lane = tid & 31, wid = tid >> 5;
    const int wm = wid / WARPS_N, wn = wid % WARPS_N;
    const int m0 = blockIdx.x * BM, n0 = blockIdx.y * BN;

    wmma::fragment<wmma::accumulator, 16, 16, 16, float> acc[FM][FN];

    // bias folded into accumulator init via 16-row broadcast tile in smem
    if (bias) {
        float* biasT = reinterpret_cast<float*>(smem);   // [16][BN]
        for (int idx = tid; idx < 16 * BN; idx += 256) biasT[idx] = bias[n0 + (idx % BN)];
        __syncthreads();
        #pragma unroll
        for (int i = 0; i < FM; i++)
            #pragma unroll
            for (int j = 0; j < FN; j++)
                wmma::load_matrix_sync(acc[i][j], biasT + wn * WN + j * 16, BN,
                                       wmma::mem_row_major);
        __syncthreads();
    } else {
        #pragma unroll
        for (int i = 0; i < FM; i++)
            #pragma unroll
            for (int j = 0; j < FN; j++) wmma::fill_fragment(acc[i][j], 0.f);
    }

    auto As = [&](int s) { return reinterpret_cast<__half*>(smem + s * ABYTES); };
    auto Bs = [&](int s) { return reinterpret_cast<__half*>(smem + 2 * ABYTES + s * BBYTES); };

    auto load_tiles = [&](int s, int k0) {
        __half* a = As(s);
        constexpr int AV = BM * BK / 8;
        #pragma unroll
        for (int v = tid; v < AV; v += 256) {
            int r = v / (BK / 8), c = (v % (BK / 8)) * 8;
            cp_async16(a + r * ASTR + c, A + (size_t)(m0 + r) * K + k0 + c);
        }
        __half* b = Bs(s);
        constexpr int BV = BK * BN / 8;
        #pragma unroll
        for (int v = tid; v < BV; v += 256) {
            int r = v / (BN / 8), c = (v % (BN / 8)) * 8;
            cp_async16(b + r * BSTR + c, Bm + (size_t)(k0 + r) * N + n0 + c);
        }
    };

    const int KT = K / BK;
    load_tiles(0, 0);
    cp_commit();

    for (int kt = 0; kt < KT; kt++) {
        const int cur = kt & 1;
        cp_wait0();
        __syncthreads();
        if (kt + 1 < KT) { load_tiles(cur ^ 1, (kt + 1) * BK); cp_commit(); }

        const __half* a = As(cur);
        const __half* b = Bs(cur);
        #pragma unroll
        for (int kk = 0; kk < BK / 16; kk++) {
            wmma::fragment<wmma::matrix_a, 16, 16, 16, __half, wmma::row_major> af[FM];
            wmma::fragment<wmma::matrix_b, 16, 16, 16, __half, wmma::row_major> bf[FN];
            #pragma unroll
            for (int i = 0; i < FM; i++)
                wmma::load_matrix_sync(af[i], a + (wm * WM + i * 16) * ASTR + kk * 16, ASTR);
            #pragma unroll
            for (int j = 0; j < FN; j++)
                wmma::load_matrix_sync(bf[j], b + (kk * 16) * BSTR + wn * WN + j * 16, BSTR);
            #pragma unroll
            for (int i = 0; i < FM; i++)
                #pragma unroll
                for (int j = 0; j < FN; j++)
                    wmma::mma_sync(acc[i][j], af[i], bf[j], acc[i][j]);
        }
        __syncthreads();
    }

    if (OUT_HALF) {
        // per-warp smem staging (aliases pipeline buffers) -> fp16 uint4 stores
        float* stageW = reinterpret_cast<float*>(smem) + wid * 16 * 20;   // [16][20]
        const int r = lane >> 1, c0 = (lane & 1) * 8;
        #pragma unroll
        for (int i = 0; i < FM; i++)
            #pragma unroll
            for (int j = 0; j < FN; j++) {
                wmma::store_matrix_sync(stageW, acc[i][j], 20, wmma::mem_row_major);
                __syncwarp();
                const float* sp = stageW + r * 20 + c0;
                __half2 h[4];
                h[0] = __floats2half2_rn(sp[0], sp[1]);
                h[1] = __floats2half2_rn(sp[2], sp[3]);
                h[2] = __floats2half2_rn(sp[4], sp[5]);
                h[3] = __floats2half2_rn(sp[6], sp[7]);
                size_t g = (size_t)(m0 + wm * WM + i * 16 + r) * N
                         + n0 + wn * WN + j * 16 + c0;
                *reinterpret_cast<uint4*>(Ch + g) = *reinterpret_cast<uint4*>(h);
                __syncwarp();
            }
    } else {
        #pragma unroll
        for (int i = 0; i < FM; i++)
            #pragma unroll
            for (int j = 0; j < FN; j++)
                wmma::store_matrix_sync(
                    Cf + (size_t)(m0 + wm * WM + i * 16) * N + n0 + wn * WN + j * 16,
                    acc[i][j], N, wmma::mem_row_major);
    }
}

// ---------------- persistent fused step loop (R6-proven, unchanged) -------
#define G_ASTR (64 + 8)
#define G_BSTR (32 + 8)
#define G_ABYTES (64 * G_ASTR * 2)
#define G_BBYTES (64 * G_BSTR * 2)

struct PersistSmem {
    float sv[A_];            // persistent: att_v kernel
    float sbias[16 * 32];    // persistent: bias broadcast tile for G
    union {
        char  gbuf[2 * (G_ABYTES + G_BBYTES)];
        struct { float hp[A_]; float sc[L_]; float att[L_]; } s;
    } u;
};

__global__ __launch_bounds__(256, 2)
void persist_loop(const float* __restrict__ v, float* __restrict__ out)
{
    __shared__ PersistSmem sm;
    const int tid = threadIdx.x, lane = tid & 31, wid = tid >> 5;
    const int cta = blockIdx.x;

    const int gm0 = (cta >> 6) * 64;
    const int gn0 = (cta & 63) * 32;
    const int wm = wid >> 1, wn = wid & 1;

    for (int j = tid; j < A_; j += 256) sm.sv[j] = v[j];
    for (int j = tid; j < 16 * 32; j += 256) sm.sbias[j] = g_hbias[gn0 + (j & 31)];
    __syncthreads();

    unsigned nbar = 0;

    for (int t = 0; t < T_; t++) {
        // Phase G: hmi = h16 @ Wh16 + hbias
        {
            wmma::fragment<wmma::accumulator, 16, 16, 16, float> acc;
            wmma::load_matrix_sync(acc, sm.sbias + wn * 16, 32, wmma::mem_row_major);

            auto As = [&](int s) { return reinterpret_cast<__half*>(sm.u.gbuf + s * (G_ABYTES + G_BBYTES)); };
            auto Bs = [&](int s) { return reinterpret_cast<__half*>(sm.u.gbuf + s * (G_ABYTES + G_BBYTES) + G_ABYTES); };
            auto load_tiles = [&](int s, int k0) {
                __half* a = As(s);
                #pragma unroll
                for (int vv = tid; vv < 64 * 64 / 8; vv += 256) {
                    int r = vv >> 3, c = (vv & 7) * 8;
                    cp_async16(a + r * G_ASTR + c, g_h16 + (size_t)(gm0 + r) * U_ + k0 + c);
                }
                __half* b = Bs(s);
                #pragma unroll
                for (int vv = tid; vv < 64 * 32 / 8; vv += 256) {
                    int r = vv >> 2, c = (vv & 3) * 8;
                    cp_async16(b + r * G_BSTR + c, g_Wh16 + (size_t)(k0 + r) * HN_ + gn0 + c);
                }
            };

            load_tiles(0, 0);
            cp_commit();
            #pragma unroll
            for (int kt = 0; kt < 8; kt++) {
                cp_wait0();
                __syncthreads();
                if (kt + 1 < 8) { load_tiles((kt + 1) & 1, (kt + 1) * 64); cp_commit(); }
                const __half* a = As(kt & 1);
                const __half* b = Bs(kt & 1);
                #pragma unroll
                for (int kk = 0; kk < 4; kk++) {
                    wmma::fragment<wmma::matrix_a, 16, 16, 16, __half, wmma::row_major> af;
                    wmma::fragment<wmma::matrix_b, 16, 16, 16, __half, wmma::row_major> bf;
                    wmma::load_matrix_sync(af, a + (wm * 16) * G_ASTR + kk * 16, G_ASTR);
                    wmma::load_matrix_sync(bf, b + (kk * 16) * G_BSTR + wn * 16, G_BSTR);
                    wmma::mma_sync(acc, af, bf, acc);
                }
                __syncthreads();
            }
            wmma::store_matrix_sync(g_hmi + (size_t)(gm0 + wm * 16) * HN_ + gn0 + wn * 16,
                                    acc, HN_, wmma::mem_row_major);
        }
        grid_sync(++nbar * 256u);

        // Phase S: attention + softmax + ctx + gates
        {
            const int b = cta;
            const float* hmi = g_hmi + b * HN_;
            for (int j = tid; j < A_; j += 256) sm.u.s.hp[j] = __ldcg(&hmi[j]);
            __syncthreads();

            const __half2* base2 = reinterpret_cast<const __half2*>(g_imgpk + (size_t)b * L_ * NF_);
            for (int l = wid; l < L_; l += 8) {
                const __half2* ip = base2 + (size_t)l * (NF_ / 2);
                float s = 0.f;
                #pragma unroll 4
                for (int a2 = lane; a2 < A_ / 2; a2 += 32) {
                    float2 f = __half22float2(ip[a2]);
                    int a = a2 * 2;
                    s += tanh_fast(f.x + sm.u.s.hp[a])     * sm.sv[a];
                    s += tanh_fast(f.y + sm.u.s.hp[a + 1]) * sm.sv[a + 1];
                }
                #pragma unroll
                for (int o = 16; o; o >>= 1) s += __shfl_xor_sync(0xffffffffu, s, o);
                if (!lane) sm.u.s.sc[l] = s;
            }
            __syncthreads();

            if (tid < 32) {
                float v1 = sm.u.s.sc[tid], v2 = sm.u.s.sc[tid + 32];
                float m = fmaxf(v1, v2);
                #pragma unroll
                for (int o = 16; o; o >>= 1) m = fmaxf(m, __shfl_xor_sync(0xffffffffu, m, o));
                float e1 = expf(v1 - m), e2 = expf(v2 - m);
                float ssum = e1 + e2;
                #pragma unroll
                for (int o = 16; o; o >>= 1) ssum += __shfl_xor_sync(0xffffffffu, ssum, o);
                float inv = 1.f / ssum;
                sm.u.s.att[tid] = e1 * inv;
                sm.u.s.att[tid + 32] = e2 * inv;
            }
            __syncthreads();

            float acc6[6] = {0.f, 0.f, 0.f, 0.f, 0.f, 0.f};
            for (int l = 0; l < L_; l++) {
                float w = sm.u.s.att[l];
                const __half2* row = base2 + (size_t)l * (NF_ / 2) + 256;
                #pragma unroll
                for (int c = 0; c < 3; c++) {
                    float2 f = __half22float2(row[tid + c * 256]);
                    acc6[2 * c]     += w * f.x;
                    acc6[2 * c + 1] += w * f.y;
                }
            }

            const float* mxt = g_mxtext + ((size_t)b * T_ + t) * U3_;
            #pragma unroll
            for (int p = 0; p < 2; p++) {
                int u = tid * 2 + p;
                float xz = mxt[u]        + acc6[p];
                float xr = mxt[512 + u]  + acc6[2 + p];
                float xh = mxt[1024 + u] + acc6[4 + p];
                float rz = __ldcg(&hmi[512 + u]);
                float rr = __ldcg(&hmi[1024 + u]);
                float rh = __ldcg(&hmi[1536 + u]);
                float z  = 1.f / (1.f + expf(-(xz + rz)));
                float r  = 1.f / (1.f + expf(-(xr + rr)));
                float hh = tanhf(xh + r * rh);
                float ho = g_h[b * U_ + u];
                float hn = z * ho + (1.f - z) * hh;
                out[((size_t)b * T_ + t) * U_ + u] = hn;
                g_h[b * U_ + u]   = hn;
                g_h16[b * U_ + u] = __float2half(hn);
            }
        }
        if (t + 1 < T_) grid_sync(++nbar * 256u);
    }
}

// ---------------- host launcher ----------------
extern "C" void kernel_launch(void* const* d_in, const int* in_sizes, int n_in,
                              void* d_out, int out_size)
{
    const float* img    = (const float*)d_in[0];
    const float* text   = (const float*)d_in[1];
    const float* kernel = (const float*)d_in[2];
    const float* ibias  = (const float*)d_in[3];
    const float* reck   = (const float*)d_in[4];
    const float* rbias  = (const float*)d_in[5];
    const float* wimg   = (const float*)d_in[6];
    const float* bimg   = (const float*)d_in[7];
    const float* attk   = (const float*)d_in[8];
    const float* attb   = (const float*)d_in[9];
    const float* vvec   = (const float*)d_in[10];
    float* out = (float*)d_out;

    void *pImg16, *pText16, *pWbig, *pWtext, *pBias2048, *pImgpk, *pMxtext;
    cudaGetSymbolAddress(&pImg16,   g_img16);
    cudaGetSymbolAddress(&pText16,  g_text16);
    cudaGetSymbolAddress(&pWbig,    g_Wbig);
    cudaGetSymbolAddress(&pWtext,   g_Wtext);
    cudaGetSymbolAddress(&pBias2048,g_bias2048);
    cudaGetSymbolAddress(&pImgpk,   g_imgpk);
    cudaGetSymbolAddress(&pMxtext,  g_mxtext);

    // dynamic smem opt-in: 2 stages of (128*(64+8) + 64*(128+8)) halves
    constexpr int GEMM_SMEM = 2 * (128 * (64 + 8) * 2 + 64 * (128 + 8) * 2);  // 71680
    cudaFuncSetAttribute(gemm_pipe<128, 128, 64, 64, 32, true>,
                         cudaFuncAttributeMaxDynamicSharedMemorySize, GEMM_SMEM);
    cudaFuncSetAttribute(gemm_pipe<128, 128, 64, 64, 32, false>,
                         cudaFuncAttributeMaxDynamicSharedMemorySize, GEMM_SMEM);

    // ---- launch order chosen so the BIG GEMM is my launch #3 (ncu lands there) --
    size_t n_img8 = (size_t)B_ * L_ * DI_ / 8;
    cvt_f32_f16_v8<<<(unsigned)((n_img8 + 255) / 256), 256>>>(img, (__half*)pImg16, n_img8);   // 0
    copy_weights<<<dim3(512, 3), 256>>>(wimg, kernel);                                         // 1
    build_misc<<<(B_ * U_ + 255) / 256, 256>>>(bimg, attb, rbias);                             // 2

    // fused: [imgproj | img_k] = img16 @ Wbig + bias2048 -> fp16 [16384, 2048]
    gemm_pipe<128, 128, 64, 64, 32, true>
        <<<dim3(16384 / 128, NF_ / 128), 256, GEMM_SMEM>>>(                                    // 3
        (const __half*)pImg16, (const __half*)pWbig, (const float*)pBias2048,
        nullptr, (__half*)pImgpk, 16384, NF_, DI_);

    size_t n_txt8 = (size_t)B_ * T_ * DT_ / 8;
    cvt_f32_f16_v8<<<(unsigned)((n_txt8 + 255) / 256), 256>>>(text, (__half*)pText16, n_txt8); // 4
    build_Wh_v8<<<(U_ * HN_ / 8) / 256, 256>>>(attk, reck);                                    // 5

    // mx_text = text16 @ Wtext + ibias -> fp32 [8192, 1536]
    gemm_pipe<128, 128, 64, 64, 32, false>
        <<<dim3(8192 / 128, U3_ / 128), 256, GEMM_SMEM>>>(                                     // 6
        (const __half*)pText16, (const __half*)pWtext, ibias,
        (float*)pMxtext, nullptr, 8192, U3_, DT_);

    // fully fused sequential GRU loop (persistent kernel, software grid sync)
    persist_loop<<<B_, 256>>>(vvec, out);                                                      // 7
}

// round 14
// speedup vs baseline: 1.0301x; 1.0301x over previous
#include <cuda_runtime.h>
#include <cuda_fp16.h>
#include <mma.h>
#include <cstddef>
#include <cstdint>

using namespace nvcuda;

// Problem dims (fixed by the dataset)
#define B_   256
#define L_   64
#define DI_  2048
#define T_   32
#define DT_  512
#define U_   512
#define A_   512
#define U3_  1536
#define HN_  2048   // combined h-GEMM output: hproj(512) | mi(1536)
#define NF_  2048   // fused img GEMM width: imgproj(512) | imgk(1536)

// ---------------- device scratch (static, allocation-free) ----------------
__device__ __half g_img16  [(size_t)B_*L_*DI_];     // fp16 img [M,K] row-major
__device__ __half g_text16 [(size_t)B_*T_*DT_];
__device__ __half g_Wbig   [(size_t)DI_*NF_];       // [wimg | wctx]  [K=2048, N=2048] row-major
__device__ __half g_Wtext  [(size_t)DT_*U3_];       // kernel[:512]   [K=512,  N=1536] row-major
__device__ float  g_bias2048[NF_];                  // [att_img_bias | 0]
__device__ __half g_Wh16   [U_*HN_];                // [att_hidden | recurrent] row-major
__device__ float  g_hbias  [HN_];
__device__ __half g_imgpk  [(size_t)B_*L_*NF_];     // fused: imgproj | imgk
__device__ float  g_mxtext [(size_t)B_*T_*U3_];     // text @ kernel[:512] + bias
__device__ float  g_hmi    [B_*HN_];                // per-step h-GEMM out
__device__ float  g_h      [B_*U_];
__device__ __half g_h16    [B_*U_];
__device__ unsigned g_barcnt;

// ---------------- small helpers ----------------
__device__ __forceinline__ float tanh_fast(float x) {
    float y; asm("tanh.approx.f32 %0, %1;" : "=f"(y) : "f"(x)); return y;
}
__device__ __forceinline__ void cp_async16(void* sm, const void* gm) {
    unsigned s = (unsigned)__cvta_generic_to_shared(sm);
    asm volatile("cp.async.cg.shared.global [%0], [%1], 16;\n" :: "r"(s), "l"(gm));
}
__device__ __forceinline__ void cp_commit() { asm volatile("cp.async.commit_group;\n"); }
__device__ __forceinline__ void cp_wait0()  { asm volatile("cp.async.wait_group 0;\n"); }

// software grid barrier (all CTAs resident by construction)
__device__ __forceinline__ void grid_sync(unsigned target) {
    __syncthreads();
    if (threadIdx.x == 0) {
        asm volatile("fence.acq_rel.gpu;" ::: "memory");
        asm volatile("red.relaxed.gpu.add.u32 [%0], 1;" :: "l"(&g_barcnt) : "memory");
        unsigned v;
        do {
            asm volatile("ld.acquire.gpu.u32 %0, [%1];" : "=r"(v) : "l"(&g_barcnt) : "memory");
            if (v < target) __nanosleep(32);
        } while (v < target);
    }
    __syncthreads();
}

// ---------------- setup kernels ----------------
// vectorized fp32 -> fp16
__global__ void cvt_f32_f16_v8(const float* __restrict__ s, __half* __restrict__ d, size_t n8) {
    size_t i = (size_t)blockIdx.x * blockDim.x + threadIdx.x;
    if (i >= n8) return;
    const float4* s4 = reinterpret_cast<const float4*>(s) + i * 2;
    float4 a = s4[0], b = s4[1];
    __half2 h[4];
    h[0] = __floats2half2_rn(a.x, a.y);
    h[1] = __floats2half2_rn(a.z, a.w);
    h[2] = __floats2half2_rn(b.x, b.y);
    h[3] = __floats2half2_rn(b.z, b.w);
    reinterpret_cast<uint4*>(d)[i] = *reinterpret_cast<uint4*>(h);
}

// copy+cvt the three K-major weight slabs (sources already [K,N] row-major)
__global__ void copy_weights(const float* __restrict__ wimg, const float* __restrict__ kernel) {
    const int job = blockIdx.y;
    const float* src; __half* dst;
    int rows, cols, dst_ld, n0out;
    if (job == 0)      { src = wimg;                       rows = DI_; cols = 512;  dst = g_Wbig;  dst_ld = NF_; n0out = 0;   }
    else if (job == 1) { src = kernel + (size_t)DT_ * U3_; rows = DI_; cols = U3_;  dst = g_Wbig;  dst_ld = NF_; n0out = 512; }
    else               { src = kernel;                     rows = DT_; cols = U3_;  dst = g_Wtext; dst_ld = U3_; n0out = 0;   }
    const int cols8 = cols / 8;
    const int total = rows * cols8;
    for (int i8 = blockIdx.x * blockDim.x + threadIdx.x; i8 < total;
         i8 += gridDim.x * blockDim.x) {
        int r = i8 / cols8, c = (i8 % cols8) * 8;
        const float* sp = src + (size_t)r * cols + c;
        float4 a = reinterpret_cast<const float4*>(sp)[0];
        float4 b = reinterpret_cast<const float4*>(sp)[1];
        __half2 h[4];
        h[0] = __floats2half2_rn(a.x, a.y);
        h[1] = __floats2half2_rn(a.z, a.w);
        h[2] = __floats2half2_rn(b.x, b.y);
        h[3] = __floats2half2_rn(b.z, b.w);
        *reinterpret_cast<uint4*>(dst + (size_t)r * dst_ld + n0out + c) =
            *reinterpret_cast<uint4*>(h);
    }
}

// Wh = [att_hidden | recurrent] fp16 row-major
__global__ void build_Wh_v8(const float* __restrict__ attk, const float* __restrict__ reck) {
    int i8 = blockIdx.x * blockDim.x + threadIdx.x;     // U_*HN_/8
    if (i8 >= U_ * HN_ / 8) return;
    int k = i8 >> 8, c = (i8 & 255) * 8;
    const float* src = (c < 512) ? (attk + (size_t)k * 512 + c)
                                 : (reck + (size_t)k * U3_ + (c - 512));
    float4 a = reinterpret_cast<const float4*>(src)[0];
    float4 b = reinterpret_cast<const float4*>(src)[1];
    __half2 h[4];
    h[0] = __floats2half2_rn(a.x, a.y);
    h[1] = __floats2half2_rn(a.z, a.w);
    h[2] = __floats2half2_rn(b.x, b.y);
    h[3] = __floats2half2_rn(b.z, b.w);
    reinterpret_cast<uint4*>(g_Wh16)[i8] = *reinterpret_cast<uint4*>(h);
}

// biases + h init + barrier reset
__global__ void build_misc(const float* __restrict__ bimg,
                           const float* __restrict__ attb, const float* __restrict__ recb) {
    int i = blockIdx.x * blockDim.x + threadIdx.x;
    if (i == 0) g_barcnt = 0;
    if (i < NF_) g_bias2048[i] = (i < 512) ? bimg[i] : 0.f;
    if (i < HN_) g_hbias[i]    = (i < 512) ? attb[i] : recb[i - 512];
    if (i < B_ * U_) { g_h[i] = 0.f; g_h16[i] = __float2half(0.f); }
}

// ---------------- cp.async double-buffered WMMA GEMM (BK=64, profiled R12) --
template<int BM, int BN, int BK, int WM, int WN, bool OUT_HALF>
__global__ __launch_bounds__(256, 2)
void gemm_pipe(const __half* __restrict__ A, const __half* __restrict__ Bm,
               const float* __restrict__ bias, float* __restrict__ Cf,
               __half* __restrict__ Ch, int M, int N, int K)
{
    constexpr int WARPS_M = BM / WM, WARPS_N = BN / WN;
    static_assert(WARPS_M * WARPS_N == 8, "8 warps");
    constexpr int FM = WM / 16, FN = WN / 16;
    constexpr int ASTR = BK + 8, BSTR = BN + 8;
    constexpr int ABYTES = BM * ASTR * 2, BBYTES = BK * BSTR * 2;
    extern __shared__ __align__(16) char smem[];

    const int tid = threadIdx.x, lane = tid & 31, wid = tid >> 5;
    const int wm = wid / WARPS_N, wn = wid % WARPS_N;
    const int m0 = blockIdx.x * BM, n0 = blockIdx.y * BN;

    wmma::fragment<wmma::accumulator, 16, 16, 16, float> acc[FM][FN];

    if (bias) {
        float* biasT = reinterpret_cast<float*>(smem);   // [16][BN]
        for (int idx = tid; idx < 16 * BN; idx += 256) biasT[idx] = bias[n0 + (idx % BN)];
        __syncthreads();
        #pragma unroll
        for (int i = 0; i < FM; i++)
            #pragma unroll
            for (int j = 0; j < FN; j++)
                wmma::load_matrix_sync(acc[i][j], biasT + wn * WN + j * 16, BN,
                                       wmma::mem_row_major);
        __syncthreads();
    } else {
        #pragma unroll
        for (int i = 0; i < FM; i++)
            #pragma unroll
            for (int j = 0; j < FN; j++) wmma::fill_fragment(acc[i][j], 0.f);
    }

    auto As = [&](int s) { return reinterpret_cast<__half*>(smem + s * ABYTES); };
    auto Bs = [&](int s) { return reinterpret_cast<__half*>(smem + 2 * ABYTES + s * BBYTES); };

    auto load_tiles = [&](int s, int k0) {
        __half* a = As(s);
        constexpr int AV = BM * BK / 8;
        #pragma unroll
        for (int v = tid; v < AV; v += 256) {
            int r = v / (BK / 8), c = (v % (BK / 8)) * 8;
            cp_async16(a + r * ASTR + c, A + (size_t)(m0 + r) * K + k0 + c);
        }
        __half* b = Bs(s);
        constexpr int BV = BK * BN / 8;
        #pragma unroll
        for (int v = tid; v < BV; v += 256) {
            int r = v / (BN / 8), c = (v % (BN / 8)) * 8;
            cp_async16(b + r * BSTR + c, Bm + (size_t)(k0 + r) * N + n0 + c);
        }
    };

    const int KT = K / BK;
    load_tiles(0, 0);
    cp_commit();

    for (int kt = 0; kt < KT; kt++) {
        const int cur = kt & 1;
        cp_wait0();
        __syncthreads();
        if (kt + 1 < KT) { load_tiles(cur ^ 1, (kt + 1) * BK); cp_commit(); }

        const __half* a = As(cur);
        const __half* b = Bs(cur);
        #pragma unroll
        for (int kk = 0; kk < BK / 16; kk++) {
            wmma::fragment<wmma::matrix_a, 16, 16, 16, __half, wmma::row_major> af[FM];
            wmma::fragment<wmma::matrix_b, 16, 16, 16, __half, wmma::row_major> bf[FN];
            #pragma unroll
            for (int i = 0; i < FM; i++)
                wmma::load_matrix_sync(af[i], a + (wm * WM + i * 16) * ASTR + kk * 16, ASTR);
            #pragma unroll
            for (int j = 0; j < FN; j++)
                wmma::load_matrix_sync(bf[j], b + (kk * 16) * BSTR + wn * WN + j * 16, BSTR);
            #pragma unroll
            for (int i = 0; i < FM; i++)
                #pragma unroll
                for (int j = 0; j < FN; j++)
                    wmma::mma_sync(acc[i][j], af[i], bf[j], acc[i][j]);
        }
        __syncthreads();
    }

    if (OUT_HALF) {
        float* stageW = reinterpret_cast<float*>(smem) + wid * 16 * 20;   // [16][20]
        const int r = lane >> 1, c0 = (lane & 1) * 8;
        #pragma unroll
        for (int i = 0; i < FM; i++)
            #pragma unroll
            for (int j = 0; j < FN; j++) {
                wmma::store_matrix_sync(stageW, acc[i][j], 20, wmma::mem_row_major);
                __syncwarp();
                const float* sp = stageW + r * 20 + c0;
                __half2 h[4];
                h[0] = __floats2half2_rn(sp[0], sp[1]);
                h[1] = __floats2half2_rn(sp[2], sp[3]);
                h[2] = __floats2half2_rn(sp[4], sp[5]);
                h[3] = __floats2half2_rn(sp[6], sp[7]);
                size_t g = (size_t)(m0 + wm * WM + i * 16 + r) * N
                         + n0 + wn * WN + j * 16 + c0;
                *reinterpret_cast<uint4*>(Ch + g) = *reinterpret_cast<uint4*>(h);
                __syncwarp();
            }
    } else {
        #pragma unroll
        for (int i = 0; i < FM; i++)
            #pragma unroll
            for (int j = 0; j < FN; j++)
                wmma::store_matrix_sync(
                    Cf + (size_t)(m0 + wm * WM + i * 16) * N + n0 + wn * WN + j * 16,
                    acc[i][j], N, wmma::mem_row_major);
    }
}

// ---------------- persistent fused step loop, REBALANCED -------------------
// 128 CTAs x 512 threads -> 1 CTA/SM on 148 SMs (no 2-CTA skew at barriers).
// Phase G: CTA c -> hmi tile [64 rows x 64 cols] (grid 4 x 32), 16 warps,
//          warp = 16x16 fragment, K=512 cp.async double-buffered.
// Phase S: CTA c -> batches 2c and 2c+1 (thread halves 0-255 / 256-511).
#define G2_STR (64 + 8)
#define G2_ABYTES (64 * G2_STR * 2)
#define G2_BBYTES (64 * G2_STR * 2)

struct PersistSmem {
    float sv[A_];              // att_v kernel (shared by both halves)
    float sbias[16 * 64];      // bias broadcast tile for G (4 KB)
    union {
        char  gbuf[2 * (G2_ABYTES + G2_BBYTES)];                 // 36.9 KB
        struct { float hp[2][A_]; float sc[2][L_]; float att[2][L_]; } s;
    } u;
};

__global__ __launch_bounds__(512, 1)
void persist_loop(const float* __restrict__ v, float* __restrict__ out)
{
    __shared__ PersistSmem sm;
    const int tid = threadIdx.x, lane = tid & 31, wid = tid >> 5;
    const int cta = blockIdx.x;                  // 0..127

    // Phase G tile coords: 4 row blocks x 32 col blocks
    const int gm0 = (cta >> 5) * 64;             // 0,64,128,192
    const int gn0 = (cta & 31) * 64;             // 0..1984 step 64
    const int wm = wid >> 2, wn = wid & 3;       // 16 warps -> 4x4 of 16x16

    // Phase S thread mapping: two batches per CTA
    const int half = tid >> 8;                   // 0 or 1
    const int t256 = tid & 255;
    const int wid8 = t256 >> 5;                  // 0..7 within half

    for (int j = tid; j < A_; j += 512) sm.sv[j] = v[j];
    for (int j = tid; j < 16 * 64; j += 512) sm.sbias[j] = g_hbias[gn0 + (j & 63)];
    __syncthreads();

    unsigned nbar = 0;

    for (int t = 0; t < T_; t++) {
        // ---------------- Phase G: hmi = h16 @ Wh16 + hbias ----------------
        {
            wmma::fragment<wmma::accumulator, 16, 16, 16, float> acc;
            wmma::load_matrix_sync(acc, sm.sbias + wn * 16, 64, wmma::mem_row_major);

            auto As = [&](int s) { return reinterpret_cast<__half*>(sm.u.gbuf + s * (G2_ABYTES + G2_BBYTES)); };
            auto Bs = [&](int s) { return reinterpret_cast<__half*>(sm.u.gbuf + s * (G2_ABYTES + G2_BBYTES) + G2_ABYTES); };
            auto load_tiles = [&](int s, int k0) {
                __half* a = As(s);
                {   // A tile: 64 rows x 64 cols -> 512 vectors, 1 per thread
                    int r = tid >> 3, c = (tid & 7) * 8;
                    cp_async16(a + r * G2_STR + c, g_h16 + (size_t)(gm0 + r) * U_ + k0 + c);
                }
                __half* b = Bs(s);
                {   // B tile: 64 rows x 64 cols -> 512 vectors, 1 per thread
                    int r = tid >> 3, c = (tid & 7) * 8;
                    cp_async16(b + r * G2_STR + c, g_Wh16 + (size_t)(k0 + r) * HN_ + gn0 + c);
                }
            };

            load_tiles(0, 0);
            cp_commit();
            #pragma unroll
            for (int kt = 0; kt < 8; kt++) {          // K=512, BK=64
                cp_wait0();
                __syncthreads();
                if (kt + 1 < 8) { load_tiles((kt + 1) & 1, (kt + 1) * 64); cp_commit(); }
                const __half* a = As(kt & 1);
                const __half* b = Bs(kt & 1);
                #pragma unroll
                for (int kk = 0; kk < 4; kk++) {
                    wmma::fragment<wmma::matrix_a, 16, 16, 16, __half, wmma::row_major> af;
                    wmma::fragment<wmma::matrix_b, 16, 16, 16, __half, wmma::row_major> bf;
                    wmma::load_matrix_sync(af, a + (wm * 16) * G2_STR + kk * 16, G2_STR);
                    wmma::load_matrix_sync(bf, b + (kk * 16) * G2_STR + wn * 16, G2_STR);
                    wmma::mma_sync(acc, af, bf, acc);
                }
                __syncthreads();
            }
            wmma::store_matrix_sync(g_hmi + (size_t)(gm0 + wm * 16) * HN_ + gn0 + wn * 16,
                                    acc, HN_, wmma::mem_row_major);
        }
        grid_sync(++nbar * 128u);

        // ---------------- Phase S: attention + softmax + ctx + gates ------
        {
            const int b = cta * 2 + half;
            const float* hmi = g_hmi + b * HN_;
            for (int j = t256; j < A_; j += 256) sm.u.s.hp[half][j] = __ldcg(&hmi[j]);
            __syncthreads();

            const __half2* base2 = reinterpret_cast<const __half2*>(g_imgpk + (size_t)b * L_ * NF_);
            const float* hp = sm.u.s.hp[half];
            for (int l = wid8; l < L_; l += 8) {
                const __half2* ip = base2 + (size_t)l * (NF_ / 2);
                float s = 0.f;
                #pragma unroll 4
                for (int a2 = lane; a2 < A_ / 2; a2 += 32) {
                    float2 f = __half22float2(ip[a2]);
                    int a = a2 * 2;
                    s += tanh_fast(f.x + hp[a])     * sm.sv[a];
                    s += tanh_fast(f.y + hp[a + 1]) * sm.sv[a + 1];
                }
                #pragma unroll
                for (int o = 16; o; o >>= 1) s += __shfl_xor_sync(0xffffffffu, s, o);
                if (!lane) sm.u.s.sc[half][l] = s;
            }
            __syncthreads();

            if (t256 < 32) {
                float v1 = sm.u.s.sc[half][t256], v2 = sm.u.s.sc[half][t256 + 32];
                float m = fmaxf(v1, v2);
                #pragma unroll
                for (int o = 16; o; o >>= 1) m = fmaxf(m, __shfl_xor_sync(0xffffffffu, m, o));
                float e1 = expf(v1 - m), e2 = expf(v2 - m);
                float ssum = e1 + e2;
                #pragma unroll
                for (int o = 16; o; o >>= 1) ssum += __shfl_xor_sync(0xffffffffu, ssum, o);
                float inv = 1.f / ssum;
                sm.u.s.att[half][t256] = e1 * inv;
                sm.u.s.att[half][t256 + 32] = e2 * inv;
            }
            __syncthreads();

            float acc6[6] = {0.f, 0.f, 0.f, 0.f, 0.f, 0.f};
            const float* att = sm.u.s.att[half];
            for (int l = 0; l < L_; l++) {
                float w = att[l];
                const __half2* row = base2 + (size_t)l * (NF_ / 2) + 256;
                #pragma unroll
                for (int c = 0; c < 3; c++) {
                    float2 f = __half22float2(row[t256 + c * 256]);
                    acc6[2 * c]     += w * f.x;
                    acc6[2 * c + 1] += w * f.y;
                }
            }

            const float* mxt = g_mxtext + ((size_t)b * T_ + t) * U3_;
            #pragma unroll
            for (int p = 0; p < 2; p++) {
                int u = t256 * 2 + p;
                float xz = mxt[u]        + acc6[p];
                float xr = mxt[512 + u]  + acc6[2 + p];
                float xh = mxt[1024 + u] + acc6[4 + p];
                float rz = __ldcg(&hmi[512 + u]);
                float rr = __ldcg(&hmi[1024 + u]);
                float rh = __ldcg(&hmi[1536 + u]);
                float z  = 1.f / (1.f + expf(-(xz + rz)));
                float r  = 1.f / (1.f + expf(-(xr + rr)));
                float hh = tanhf(xh + r * rh);
                float ho = g_h[b * U_ + u];
                float hn = z * ho + (1.f - z) * hh;
                out[((size_t)b * T_ + t) * U_ + u] = hn;
                g_h[b * U_ + u]   = hn;
                g_h16[b * U_ + u] = __float2half(hn);
            }
        }
        if (t + 1 < T_) grid_sync(++nbar * 128u);
    }
}

// ---------------- host launcher ----------------
extern "C" void kernel_launch(void* const* d_in, const int* in_sizes, int n_in,
                              void* d_out, int out_size)
{
    const float* img    = (const float*)d_in[0];
    const float* text   = (const float*)d_in[1];
    const float* kernel = (const float*)d_in[2];
    const float* ibias  = (const float*)d_in[3];
    const float* reck   = (const float*)d_in[4];
    const float* rbias  = (const float*)d_in[5];
    const float* wimg   = (const float*)d_in[6];
    const float* bimg   = (const float*)d_in[7];
    const float* attk   = (const float*)d_in[8];
    const float* attb   = (const float*)d_in[9];
    const float* vvec   = (const float*)d_in[10];
    float* out = (float*)d_out;

    void *pImg16, *pText16, *pWbig, *pWtext, *pBias2048, *pImgpk, *pMxtext;
    cudaGetSymbolAddress(&pImg16,   g_img16);
    cudaGetSymbolAddress(&pText16,  g_text16);
    cudaGetSymbolAddress(&pWbig,    g_Wbig);
    cudaGetSymbolAddress(&pWtext,   g_Wtext);
    cudaGetSymbolAddress(&pBias2048,g_bias2048);
    cudaGetSymbolAddress(&pImgpk,   g_imgpk);
    cudaGetSymbolAddress(&pMxtext,  g_mxtext);

    constexpr int GEMM_SMEM = 2 * (128 * (64 + 8) * 2 + 64 * (128 + 8) * 2);  // 71680
    cudaFuncSetAttribute(gemm_pipe<128, 128, 64, 64, 32, true>,
                         cudaFuncAttributeMaxDynamicSharedMemorySize, GEMM_SMEM);
    cudaFuncSetAttribute(gemm_pipe<128, 128, 64, 64, 32, false>,
                         cudaFuncAttributeMaxDynamicSharedMemorySize, GEMM_SMEM);

    // ---- launch order: big GEMM stays launch #3 (ncu lands there) ----------
    size_t n_img8 = (size_t)B_ * L_ * DI_ / 8;
    cvt_f32_f16_v8<<<(unsigned)((n_img8 + 255) / 256), 256>>>(img, (__half*)pImg16, n_img8);   // 0
    copy_weights<<<dim3(512, 3), 256>>>(wimg, kernel);                                         // 1
    build_misc<<<(B_ * U_ + 255) / 256, 256>>>(bimg, attb, rbias);                             // 2

    // fused: [imgproj | img_k] = img16 @ Wbig + bias2048 -> fp16 [16384, 2048]
    gemm_pipe<128, 128, 64, 64, 32, true>
        <<<dim3(16384 / 128, NF_ / 128), 256, GEMM_SMEM>>>(                                    // 3
        (const __half*)pImg16, (const __half*)pWbig, (const float*)pBias2048,
        nullptr, (__half*)pImgpk, 16384, NF_, DI_);

    size_t n_txt8 = (size_t)B_ * T_ * DT_ / 8;
    cvt_f32_f16_v8<<<(unsigned)((n_txt8 + 255) / 256), 256>>>(text, (__half*)pText16, n_txt8); // 4
    build_Wh_v8<<<(U_ * HN_ / 8) / 256, 256>>>(attk, reck);                                    // 5

    // mx_text = text16 @ Wtext + ibias -> fp32 [8192, 1536]
    gemm_pipe<128, 128, 64, 64, 32, false>
        <<<dim3(8192 / 128, U3_ / 128), 256, GEMM_SMEM>>>(                                     // 6
        (const __half*)pText16, (const __half*)pWtext, ibias,
        (float*)pMxtext, nullptr, 8192, U3_, DT_);

    // rebalanced persistent GRU loop: 128 CTAs x 512 threads, 1 CTA/SM
    persist_loop<<<128, 512>>>(vvec, out);                                                     // 7
}

// round 15
// speedup vs baseline: 1.0593x; 1.0283x over previous
#include <cuda_runtime.h>
#include <cuda_fp16.h>
#include <mma.h>
#include <cstddef>
#include <cstdint>

using namespace nvcuda;

// Problem dims (fixed by the dataset)
#define B_   256
#define L_   64
#define DI_  2048
#define T_   32
#define DT_  512
#define U_   512
#define A_   512
#define U3_  1536
#define HN_  2048   // combined h-GEMM output: hproj(512) | mi(1536)
#define NF_  2048   // fused img GEMM width: imgproj(512) | imgk(1536)

// ---------------- device scratch (static, allocation-free) ----------------
__device__ __half g_img16  [(size_t)B_*L_*DI_];     // fp16 img [M,K] row-major
__device__ __half g_text16 [(size_t)B_*T_*DT_];
__device__ __half g_Wbig   [(size_t)DI_*NF_];       // [wimg | wctx]  [K=2048, N=2048] row-major
__device__ __half g_Wtext  [(size_t)DT_*U3_];       // kernel[:512]   [K=512,  N=1536] row-major
__device__ float  g_bias2048[NF_];                  // [att_img_bias | 0]
__device__ __half g_Wh16   [U_*HN_];                // [att_hidden | recurrent] row-major
__device__ float  g_hbias  [HN_];
__device__ __half g_imgpk  [(size_t)B_*L_*NF_];     // fused: imgproj | imgk
__device__ float  g_mxtext [(size_t)B_*T_*U3_];     // text @ kernel[:512] + bias
__device__ float  g_hmi    [B_*HN_];                // per-step h-GEMM out
__device__ float  g_h      [B_*U_];
__device__ __half g_h16    [B_*U_];
__device__ unsigned g_barcnt;

// ---------------- small helpers ----------------
__device__ __forceinline__ __half2 tanh2_fast(__half2 x) {
    uint32_t xi = *reinterpret_cast<uint32_t*>(&x), yi;
    asm("tanh.approx.f16x2 %0, %1;" : "=r"(yi) : "r"(xi));
    return *reinterpret_cast<__half2*>(&yi);
}
__device__ __forceinline__ void cp_async16(void* sm, const void* gm) {
    unsigned s = (unsigned)__cvta_generic_to_shared(sm);
    asm volatile("cp.async.cg.shared.global [%0], [%1], 16;\n" :: "r"(s), "l"(gm));
}
__device__ __forceinline__ void cp_commit() { asm volatile("cp.async.commit_group;\n"); }
__device__ __forceinline__ void cp_wait0()  { asm volatile("cp.async.wait_group 0;\n"); }

// software grid barrier (all CTAs resident by construction)
__device__ __forceinline__ void grid_sync(unsigned target) {
    __syncthreads();
    if (threadIdx.x == 0) {
        asm volatile("fence.acq_rel.gpu;" ::: "memory");
        asm volatile("red.relaxed.gpu.add.u32 [%0], 1;" :: "l"(&g_barcnt) : "memory");
        unsigned v;
        do {
            asm volatile("ld.acquire.gpu.u32 %0, [%1];" : "=r"(v) : "l"(&g_barcnt) : "memory");
            if (v < target) __nanosleep(32);
        } while (v < target);
    }
    __syncthreads();
}

// ---------------- setup kernels ----------------
// vectorized fp32 -> fp16
__global__ void cvt_f32_f16_v8(const float* __restrict__ s, __half* __restrict__ d, size_t n8) {
    size_t i = (size_t)blockIdx.x * blockDim.x + threadIdx.x;
    if (i >= n8) return;
    const float4* s4 = reinterpret_cast<const float4*>(s) + i * 2;
    float4 a = s4[0], b = s4[1];
    __half2 h[4];
    h[0] = __floats2half2_rn(a.x, a.y);
    h[1] = __floats2half2_rn(a.z, a.w);
    h[2] = __floats2half2_rn(b.x, b.y);
    h[3] = __floats2half2_rn(b.z, b.w);
    reinterpret_cast<uint4*>(d)[i] = *reinterpret_cast<uint4*>(h);
}

// copy+cvt the three K-major weight slabs (sources already [K,N] row-major)
__global__ void copy_weights(const float* __restrict__ wimg, const float* __restrict__ kernel) {
    const int job = blockIdx.y;
    const float* src; __half* dst;
    int rows, cols, dst_ld, n0out;
    if (job == 0)      { src = wimg;                       rows = DI_; cols = 512;  dst = g_Wbig;  dst_ld = NF_; n0out = 0;   }
    else if (job == 1) { src = kernel + (size_t)DT_ * U3_; rows = DI_; cols = U3_;  dst = g_Wbig;  dst_ld = NF_; n0out = 512; }
    else               { src = kernel;                     rows = DT_; cols = U3_;  dst = g_Wtext; dst_ld = U3_; n0out = 0;   }
    const int cols8 = cols / 8;
    const int total = rows * cols8;
    for (int i8 = blockIdx.x * blockDim.x + threadIdx.x; i8 < total;
         i8 += gridDim.x * blockDim.x) {
        int r = i8 / cols8, c = (i8 % cols8) * 8;
        const float* sp = src + (size_t)r * cols + c;
        float4 a = reinterpret_cast<const float4*>(sp)[0];
        float4 b = reinterpret_cast<const float4*>(sp)[1];
        __half2 h[4];
        h[0] = __floats2half2_rn(a.x, a.y);
        h[1] = __floats2half2_rn(a.z, a.w);
        h[2] = __floats2half2_rn(b.x, b.y);
        h[3] = __floats2half2_rn(b.z, b.w);
        *reinterpret_cast<uint4*>(dst + (size_t)r * dst_ld + n0out + c) =
            *reinterpret_cast<uint4*>(h);
    }
}

// Wh = [att_hidden | recurrent] fp16 row-major
__global__ void build_Wh_v8(const float* __restrict__ attk, const float* __restrict__ reck) {
    int i8 = blockIdx.x * blockDim.x + threadIdx.x;     // U_*HN_/8
    if (i8 >= U_ * HN_ / 8) return;
    int k = i8 >> 8, c = (i8 & 255) * 8;
    const float* src = (c < 512) ? (attk + (size_t)k * 512 + c)
                                 : (reck + (size_t)k * U3_ + (c - 512));
    float4 a = reinterpret_cast<const float4*>(src)[0];
    float4 b = reinterpret_cast<const float4*>(src)[1];
    __half2 h[4];
    h[0] = __floats2half2_rn(a.x, a.y);
    h[1] = __floats2half2_rn(a.z, a.w);
    h[2] = __floats2half2_rn(b.x, b.y);
    h[3] = __floats2half2_rn(b.z, b.w);
    reinterpret_cast<uint4*>(g_Wh16)[i8] = *reinterpret_cast<uint4*>(h);
}

// biases + h init + barrier reset
__global__ void build_misc(const float* __restrict__ bimg,
                           const float* __restrict__ attb, const float* __restrict__ recb) {
    int i = blockIdx.x * blockDim.x + threadIdx.x;
    if (i == 0) g_barcnt = 0;
    if (i < NF_) g_bias2048[i] = (i < 512) ? bimg[i] : 0.f;
    if (i < HN_) g_hbias[i]    = (i < 512) ? attb[i] : recb[i - 512];
    if (i < B_ * U_) { g_h[i] = 0.f; g_h16[i] = __float2half(0.f); }
}

// ---------------- cp.async double-buffered WMMA GEMM (BK=64, profiled) -----
template<int BM, int BN, int BK, int WM, int WN, bool OUT_HALF>
__global__ __launch_bounds__(256, 2)
void gemm_pipe(const __half* __restrict__ A, const __half* __restrict__ Bm,
               const float* __restrict__ bias, float* __restrict__ Cf,
               __half* __restrict__ Ch, int M, int N, int K)
{
    constexpr int WARPS_M = BM / WM, WARPS_N = BN / WN;
    static_assert(WARPS_M * WARPS_N == 8, "8 warps");
    constexpr int FM = WM / 16, FN = WN / 16;
    constexpr int ASTR = BK + 8, BSTR = BN + 8;
    constexpr int ABYTES = BM * ASTR * 2, BBYTES = BK * BSTR * 2;
    extern __shared__ __align__(16) char smem[];

    const int tid = threadIdx.x, lane = tid & 31, wid = tid >> 5;
    const int wm = wid / WARPS_N, wn = wid % WARPS_N;
    const int m0 = blockIdx.x * BM, n0 = blockIdx.y * BN;

    wmma::fragment<wmma::accumulator, 16, 16, 16, float> acc[FM][FN];

    if (bias) {
        float* biasT = reinterpret_cast<float*>(smem);   // [16][BN]
        for (int idx = tid; idx < 16 * BN; idx += 256) biasT[idx] = bias[n0 + (idx % BN)];
        __syncthreads();
        #pragma unroll
        for (int i = 0; i < FM; i++)
            #pragma unroll
            for (int j = 0; j < FN; j++)
                wmma::load_matrix_sync(acc[i][j], biasT + wn * WN + j * 16, BN,
                                       wmma::mem_row_major);
        __syncthreads();
    } else {
        #pragma unroll
        for (int i = 0; i < FM; i++)
            #pragma unroll
            for (int j = 0; j < FN; j++) wmma::fill_fragment(acc[i][j], 0.f);
    }

    auto As = [&](int s) { return reinterpret_cast<__half*>(smem + s * ABYTES); };
    auto Bs = [&](int s) { return reinterpret_cast<__half*>(smem + 2 * ABYTES + s * BBYTES); };

    auto load_tiles = [&](int s, int k0) {
        __half* a = As(s);
        constexpr int AV = BM * BK / 8;
        #pragma unroll
        for (int v = tid; v < AV; v += 256) {
            int r = v / (BK / 8), c = (v % (BK / 8)) * 8;
            cp_async16(a + r * ASTR + c, A + (size_t)(m0 + r) * K + k0 + c);
        }
        __half* b = Bs(s);
        constexpr int BV = BK * BN / 8;
        #pragma unroll
        for (int v = tid; v < BV; v += 256) {
            int r = v / (BN / 8), c = (v % (BN / 8)) * 8;
            cp_async16(b + r * BSTR + c, Bm + (size_t)(k0 + r) * N + n0 + c);
        }
    };

    const int KT = K / BK;
    load_tiles(0, 0);
    cp_commit();

    for (int kt = 0; kt < KT; kt++) {
        const int cur = kt & 1;
        cp_wait0();
        __syncthreads();
        if (kt + 1 < KT) { load_tiles(cur ^ 1, (kt + 1) * BK); cp_commit(); }

        const __half* a = As(cur);
        const __half* b = Bs(cur);
        #pragma unroll
        for (int kk = 0; kk < BK / 16; kk++) {
            wmma::fragment<wmma::matrix_a, 16, 16, 16, __half, wmma::row_major> af[FM];
            wmma::fragment<wmma::matrix_b, 16, 16, 16, __half, wmma::row_major> bf[FN];
            #pragma unroll
            for (int i = 0; i < FM; i++)
                wmma::load_matrix_sync(af[i], a + (wm * WM + i * 16) * ASTR + kk * 16, ASTR);
            #pragma unroll
            for (int j = 0; j < FN; j++)
                wmma::load_matrix_sync(bf[j], b + (kk * 16) * BSTR + wn * WN + j * 16, BSTR);
            #pragma unroll
            for (int i = 0; i < FM; i++)
                #pragma unroll
                for (int j = 0; j < FN; j++)
                    wmma::mma_sync(acc[i][j], af[i], bf[j], acc[i][j]);
        }
        __syncthreads();
    }

    if (OUT_HALF) {
        float* stageW = reinterpret_cast<float*>(smem) + wid * 16 * 20;   // [16][20]
        const int r = lane >> 1, c0 = (lane & 1) * 8;
        #pragma unroll
        for (int i = 0; i < FM; i++)
            #pragma unroll
            for (int j = 0; j < FN; j++) {
                wmma::store_matrix_sync(stageW, acc[i][j], 20, wmma::mem_row_major);
                __syncwarp();
                const float* sp = stageW + r * 20 + c0;
                __half2 h[4];
                h[0] = __floats2half2_rn(sp[0], sp[1]);
                h[1] = __floats2half2_rn(sp[2], sp[3]);
                h[2] = __floats2half2_rn(sp[4], sp[5]);
                h[3] = __floats2half2_rn(sp[6], sp[7]);
                size_t g = (size_t)(m0 + wm * WM + i * 16 + r) * N
                         + n0 + wn * WN + j * 16 + c0;
                *reinterpret_cast<uint4*>(Ch + g) = *reinterpret_cast<uint4*>(h);
                __syncwarp();
            }
    } else {
        #pragma unroll
        for (int i = 0; i < FM; i++)
            #pragma unroll
            for (int j = 0; j < FN; j++)
                wmma::store_matrix_sync(
                    Cf + (size_t)(m0 + wm * WM + i * 16) * N + n0 + wn * WN + j * 16,
                    acc[i][j], N, wmma::mem_row_major);
    }
}

// ---------------- persistent fused step loop ----------------
// 128 CTAs x 512 threads, 1 CTA/SM. Phase G: 64x64 hmi tile per CTA.
// Phase S: 2 batches per CTA (thread halves). Scores use packed f16x2 tanh.
#define G2_STR (64 + 8)
#define G2_ABYTES (64 * G2_STR * 2)
#define G2_BBYTES (64 * G2_STR * 2)

struct PersistSmem {
    float sv[A_];              // att_v kernel (fp32, read as float2)
    float sbias[16 * 64];      // bias broadcast tile for G
    union {
        char  gbuf[2 * (G2_ABYTES + G2_BBYTES)];                 // 36.9 KB
        struct { __half2 hp2[2][A_ / 2]; float sc[2][L_]; float att[2][L_]; } s;
    } u;
};

__global__ __launch_bounds__(512, 1)
void persist_loop(const float* __restrict__ v, float* __restrict__ out)
{
    __shared__ PersistSmem sm;
    const int tid = threadIdx.x, lane = tid & 31, wid = tid >> 5;
    const int cta = blockIdx.x;                  // 0..127

    // Phase G tile coords: 4 row blocks x 32 col blocks
    const int gm0 = (cta >> 5) * 64;
    const int gn0 = (cta & 31) * 64;
    const int wm = wid >> 2, wn = wid & 3;       // 16 warps -> 4x4 of 16x16

    // Phase S thread mapping: two batches per CTA
    const int half = tid >> 8;                   // 0 or 1
    const int t256 = tid & 255;
    const int wid8 = t256 >> 5;                  // 0..7 within half

    for (int j = tid; j < A_; j += 512) sm.sv[j] = v[j];
    for (int j = tid; j < 16 * 64; j += 512) sm.sbias[j] = g_hbias[gn0 + (j & 63)];
    __syncthreads();

    unsigned nbar = 0;

    for (int t = 0; t < T_; t++) {
        // ---------------- Phase G: hmi = h16 @ Wh16 + hbias ----------------
        {
            wmma::fragment<wmma::accumulator, 16, 16, 16, float> acc;
            wmma::load_matrix_sync(acc, sm.sbias + wn * 16, 64, wmma::mem_row_major);

            auto As = [&](int s) { return reinterpret_cast<__half*>(sm.u.gbuf + s * (G2_ABYTES + G2_BBYTES)); };
            auto Bs = [&](int s) { return reinterpret_cast<__half*>(sm.u.gbuf + s * (G2_ABYTES + G2_BBYTES) + G2_ABYTES); };
            auto load_tiles = [&](int s, int k0) {
                __half* a = As(s);
                {   int r = tid >> 3, c = (tid & 7) * 8;
                    cp_async16(a + r * G2_STR + c, g_h16 + (size_t)(gm0 + r) * U_ + k0 + c); }
                __half* b = Bs(s);
                {   int r = tid >> 3, c = (tid & 7) * 8;
                    cp_async16(b + r * G2_STR + c, g_Wh16 + (size_t)(k0 + r) * HN_ + gn0 + c); }
            };

            load_tiles(0, 0);
            cp_commit();
            #pragma unroll
            for (int kt = 0; kt < 8; kt++) {          // K=512, BK=64
                cp_wait0();
                __syncthreads();
                if (kt + 1 < 8) { load_tiles((kt + 1) & 1, (kt + 1) * 64); cp_commit(); }
                const __half* a = As(kt & 1);
                const __half* b = Bs(kt & 1);
                #pragma unroll
                for (int kk = 0; kk < 4; kk++) {
                    wmma::fragment<wmma::matrix_a, 16, 16, 16, __half, wmma::row_major> af;
                    wmma::fragment<wmma::matrix_b, 16, 16, 16, __half, wmma::row_major> bf;
                    wmma::load_matrix_sync(af, a + (wm * 16) * G2_STR + kk * 16, G2_STR);
                    wmma::load_matrix_sync(bf, b + (kk * 16) * G2_STR + wn * 16, G2_STR);
                    wmma::mma_sync(acc, af, bf, acc);
                }
                __syncthreads();
            }
            wmma::store_matrix_sync(g_hmi + (size_t)(gm0 + wm * 16) * HN_ + gn0 + wn * 16,
                                    acc, HN_, wmma::mem_row_major);
        }
        grid_sync(++nbar * 128u);

        // ---------------- Phase S: attention + softmax + ctx + gates ------
        {
            const int b = cta * 2 + half;
            const float* hmi = g_hmi + b * HN_;
            // hp as packed half2 (one element per thread)
            {
                int j = t256;                        // A_/2 == 256
                float a0 = __ldcg(&hmi[2 * j]);
                float a1 = __ldcg(&hmi[2 * j + 1]);
                sm.u.s.hp2[half][j] = __floats2half2_rn(a0, a1);
            }
            __syncthreads();

            const __half2* base2 = reinterpret_cast<const __half2*>(g_imgpk + (size_t)b * L_ * NF_);
            const __half2* hp2 = sm.u.s.hp2[half];
            const float2*  sv2 = reinterpret_cast<const float2*>(sm.sv);
            for (int l = wid8; l < L_; l += 8) {
                const __half2* ip = base2 + (size_t)l * (NF_ / 2);
                float s = 0.f;
                #pragma unroll 4
                for (int a2 = lane; a2 < A_ / 2; a2 += 32) {
                    __half2 t2 = tanh2_fast(__hadd2(ip[a2], hp2[a2]));
                    float2 tf = __half22float2(t2);
                    float2 vv = sv2[a2];
                    s += tf.x * vv.x + tf.y * vv.y;
                }
                #pragma unroll
                for (int o = 16; o; o >>= 1) s += __shfl_xor_sync(0xffffffffu, s, o);
                if (!lane) sm.u.s.sc[half][l] = s;
            }
            __syncthreads();

            if (t256 < 32) {
                float v1 = sm.u.s.sc[half][t256], v2 = sm.u.s.sc[half][t256 + 32];
                float m = fmaxf(v1, v2);
                #pragma unroll
                for (int o = 16; o; o >>= 1) m = fmaxf(m, __shfl_xor_sync(0xffffffffu, m, o));
                float e1 = expf(v1 - m), e2 = expf(v2 - m);
                float ssum = e1 + e2;
                #pragma unroll
                for (int o = 16; o; o >>= 1) ssum += __shfl_xor_sync(0xffffffffu, ssum, o);
                float inv = 1.f / ssum;
                sm.u.s.att[half][t256] = e1 * inv;
                sm.u.s.att[half][t256 + 32] = e2 * inv;
            }
            __syncthreads();

            // ctx-projected: cols [512,2048) of fused buffer, 2-way l-unroll
            float acc6[6] = {0.f, 0.f, 0.f, 0.f, 0.f, 0.f};
            const float* att = sm.u.s.att[half];
            for (int l = 0; l < L_; l += 2) {
                float w0 = att[l], w1 = att[l + 1];
                const __half2* r0 = base2 + (size_t)l * (NF_ / 2) + 256;
                const __half2* r1 = r0 + (NF_ / 2);
                #pragma unroll
                for (int c = 0; c < 3; c++) {
                    float2 f0 = __half22float2(r0[t256 + c * 256]);
                    float2 f1 = __half22float2(r1[t256 + c * 256]);
                    acc6[2 * c]     += w0 * f0.x + w1 * f1.x;
                    acc6[2 * c + 1] += w0 * f0.y + w1 * f1.y;
                }
            }

            const float* mxt = g_mxtext + ((size_t)b * T_ + t) * U3_;
            #pragma unroll
            for (int p = 0; p < 2; p++) {
                int u = t256 * 2 + p;
                float xz = mxt[u]        + acc6[p];
                float xr = mxt[512 + u]  + acc6[2 + p];
                float xh = mxt[1024 + u] + acc6[4 + p];
                float rz = __ldcg(&hmi[512 + u]);
                float rr = __ldcg(&hmi[1024 + u]);
                float rh = __ldcg(&hmi[1536 + u]);
                float z  = 1.f / (1.f + expf(-(xz + rz)));
                float r  = 1.f / (1.f + expf(-(xr + rr)));
                float hh = tanhf(xh + r * rh);
                float ho = g_h[b * U_ + u];
                float hn = z * ho + (1.f - z) * hh;
                out[((size_t)b * T_ + t) * U_ + u] = hn;
                g_h[b * U_ + u]   = hn;
                g_h16[b * U_ + u] = __float2half(hn);
            }
        }
        if (t + 1 < T_) grid_sync(++nbar * 128u);
    }
}

// ---------------- host launcher ----------------
extern "C" void kernel_launch(void* const* d_in, const int* in_sizes, int n_in,
                              void* d_out, int out_size)
{
    const float* img    = (const float*)d_in[0];
    const float* text   = (const float*)d_in[1];
    const float* kernel = (const float*)d_in[2];
    const float* ibias  = (const float*)d_in[3];
    const float* reck   = (const float*)d_in[4];
    const float* rbias  = (const float*)d_in[5];
    const float* wimg   = (const float*)d_in[6];
    const float* bimg   = (const float*)d_in[7];
    const float* attk   = (const float*)d_in[8];
    const float* attb   = (const float*)d_in[9];
    const float* vvec   = (const float*)d_in[10];
    float* out = (float*)d_out;

    void *pImg16, *pText16, *pWbig, *pWtext, *pBias2048, *pImgpk, *pMxtext;
    cudaGetSymbolAddress(&pImg16,   g_img16);
    cudaGetSymbolAddress(&pText16,  g_text16);
    cudaGetSymbolAddress(&pWbig,    g_Wbig);
    cudaGetSymbolAddress(&pWtext,   g_Wtext);
    cudaGetSymbolAddress(&pBias2048,g_bias2048);
    cudaGetSymbolAddress(&pImgpk,   g_imgpk);
    cudaGetSymbolAddress(&pMxtext,  g_mxtext);

    constexpr int GEMM_SMEM = 2 * (128 * (64 + 8) * 2 + 64 * (128 + 8) * 2);  // 71680
    cudaFuncSetAttribute(gemm_pipe<128, 128, 64, 64, 32, true>,
                         cudaFuncAttributeMaxDynamicSharedMemorySize, GEMM_SMEM);
    cudaFuncSetAttribute(gemm_pipe<128, 128, 64, 64, 32, false>,
                         cudaFuncAttributeMaxDynamicSharedMemorySize, GEMM_SMEM);

    // ---- launch order: big GEMM stays launch #3 (ncu lands there) ----------
    size_t n_img8 = (size_t)B_ * L_ * DI_ / 8;
    cvt_f32_f16_v8<<<(unsigned)((n_img8 + 255) / 256), 256>>>(img, (__half*)pImg16, n_img8);   // 0
    copy_weights<<<dim3(512, 3), 256>>>(wimg, kernel);                                         // 1
    build_misc<<<(B_ * U_ + 255) / 256, 256>>>(bimg, attb, rbias);                             // 2

    // fused: [imgproj | img_k] = img16 @ Wbig + bias2048 -> fp16 [16384, 2048]
    gemm_pipe<128, 128, 64, 64, 32, true>
        <<<dim3(16384 / 128, NF_ / 128), 256, GEMM_SMEM>>>(                                    // 3
        (const __half*)pImg16, (const __half*)pWbig, (const float*)pBias2048,
        nullptr, (__half*)pImgpk, 16384, NF_, DI_);

    size_t n_txt8 = (size_t)B_ * T_ * DT_ / 8;
    cvt_f32_f16_v8<<<(unsigned)((n_txt8 + 255) / 256), 256>>>(text, (__half*)pText16, n_txt8); // 4
    build_Wh_v8<<<(U_ * HN_ / 8) / 256, 256>>>(attk, reck);                                    // 5

    // mx_text = text16 @ Wtext + ibias -> fp32 [8192, 1536]
    gemm_pipe<128, 128, 64, 64, 32, false>
        <<<dim3(8192 / 128, U3_ / 128), 256, GEMM_SMEM>>>(                                     // 6
        (const __half*)pText16, (const __half*)pWtext, ibias,
        (float*)pMxtext, nullptr, 8192, U3_, DT_);

    // persistent GRU loop: 128 CTAs x 512 threads, 1 CTA/SM
    persist_loop<<<128, 512>>>(vvec, out);                                                     // 7
}

// round 16
// speedup vs baseline: 1.0785x; 1.0181x over previous
#include <cuda_runtime.h>
#include <cuda_fp16.h>
#include <mma.h>
#include <cstddef>
#include <cstdint>

using namespace nvcuda;

// Problem dims (fixed by the dataset)
#define B_   256
#define L_   64
#define DI_  2048
#define T_   32
#define DT_  512
#define U_   512
#define A_   512
#define U3_  1536
#define HN_  2048   // combined h-GEMM output: hproj(512) | mi(1536)
#define NF_  2048   // fused img GEMM width: imgproj(512) | imgk(1536)

// ---------------- device scratch (static, allocation-free) ----------------
__device__ __half g_img16  [(size_t)B_*L_*DI_];     // fp16 img [M,K] row-major
__device__ __half g_text16 [(size_t)B_*T_*DT_];
__device__ __half g_Wbig   [(size_t)DI_*NF_];       // [wimg | wctx]  [K=2048, N=2048] row-major
__device__ __half g_Wtext  [(size_t)DT_*U3_];       // kernel[:512]   [K=512,  N=1536] row-major
__device__ float  g_bias2048[NF_];                  // [att_img_bias | 0]
__device__ __half g_Wh16   [U_*HN_];                // [att_hidden | recurrent] row-major
__device__ float  g_hbias  [HN_];
__device__ __half g_imgpk  [(size_t)B_*L_*NF_];     // fused: imgproj | imgk
__device__ float  g_mxtext [(size_t)B_*T_*U3_];     // text @ kernel[:512] + bias
__device__ float  g_hmi    [B_*HN_];                // per-step h-GEMM out
__device__ float  g_h      [B_*U_];
__device__ __half g_h16    [B_*U_];
__device__ unsigned g_barcnt;

// ---------------- small helpers ----------------
__device__ __forceinline__ __half2 tanh2_fast(__half2 x) {
    uint32_t xi = *reinterpret_cast<uint32_t*>(&x), yi;
    asm("tanh.approx.f16x2 %0, %1;" : "=r"(yi) : "r"(xi));
    return *reinterpret_cast<__half2*>(&yi);
}
__device__ __forceinline__ void cp_async16(void* sm, const void* gm) {
    unsigned s = (unsigned)__cvta_generic_to_shared(sm);
    asm volatile("cp.async.cg.shared.global [%0], [%1], 16;\n" :: "r"(s), "l"(gm));
}
__device__ __forceinline__ void cp_commit() { asm volatile("cp.async.commit_group;\n"); }
__device__ __forceinline__ void cp_wait0()  { asm volatile("cp.async.wait_group 0;\n"); }

// software grid barrier (all CTAs resident by construction)
__device__ __forceinline__ void grid_sync(unsigned target) {
    __syncthreads();
    if (threadIdx.x == 0) {
        asm volatile("fence.acq_rel.gpu;" ::: "memory");
        asm volatile("red.relaxed.gpu.add.u32 [%0], 1;" :: "l"(&g_barcnt) : "memory");
        unsigned v;
        do {
            asm volatile("ld.acquire.gpu.u32 %0, [%1];" : "=r"(v) : "l"(&g_barcnt) : "memory");
            if (v < target) __nanosleep(32);
        } while (v < target);
    }
    __syncthreads();
}

// ---------------- setup kernels ----------------
// vectorized fp32 -> fp16
__global__ void cvt_f32_f16_v8(const float* __restrict__ s, __half* __restrict__ d, size_t n8) {
    size_t i = (size_t)blockIdx.x * blockDim.x + threadIdx.x;
    if (i >= n8) return;
    const float4* s4 = reinterpret_cast<const float4*>(s) + i * 2;
    float4 a = s4[0], b = s4[1];
    __half2 h[4];
    h[0] = __floats2half2_rn(a.x, a.y);
    h[1] = __floats2half2_rn(a.z, a.w);
    h[2] = __floats2half2_rn(b.x, b.y);
    h[3] = __floats2half2_rn(b.z, b.w);
    reinterpret_cast<uint4*>(d)[i] = *reinterpret_cast<uint4*>(h);
}

// copy+cvt the three K-major weight slabs (sources already [K,N] row-major)
__global__ void copy_weights(const float* __restrict__ wimg, const float* __restrict__ kernel) {
    const int job = blockIdx.y;
    const float* src; __half* dst;
    int rows, cols, dst_ld, n0out;
    if (job == 0)      { src = wimg;                       rows = DI_; cols = 512;  dst = g_Wbig;  dst_ld = NF_; n0out = 0;   }
    else if (job == 1) { src = kernel + (size_t)DT_ * U3_; rows = DI_; cols = U3_;  dst = g_Wbig;  dst_ld = NF_; n0out = 512; }
    else               { src = kernel;                     rows = DT_; cols = U3_;  dst = g_Wtext; dst_ld = U3_; n0out = 0;   }
    const int cols8 = cols / 8;
    const int total = rows * cols8;
    for (int i8 = blockIdx.x * blockDim.x + threadIdx.x; i8 < total;
         i8 += gridDim.x * blockDim.x) {
        int r = i8 / cols8, c = (i8 % cols8) * 8;
        const float* sp = src + (size_t)r * cols + c;
        float4 a = reinterpret_cast<const float4*>(sp)[0];
        float4 b = reinterpret_cast<const float4*>(sp)[1];
        __half2 h[4];
        h[0] = __floats2half2_rn(a.x, a.y);
        h[1] = __floats2half2_rn(a.z, a.w);
        h[2] = __floats2half2_rn(b.x, b.y);
        h[3] = __floats2half2_rn(b.z, b.w);
        *reinterpret_cast<uint4*>(dst + (size_t)r * dst_ld + n0out + c) =
            *reinterpret_cast<uint4*>(h);
    }
}

// Wh = [att_hidden | recurrent] fp16 row-major
__global__ void build_Wh_v8(const float* __restrict__ attk, const float* __restrict__ reck) {
    int i8 = blockIdx.x * blockDim.x + threadIdx.x;     // U_*HN_/8
    if (i8 >= U_ * HN_ / 8) return;
    int k = i8 >> 8, c = (i8 & 255) * 8;
    const float* src = (c < 512) ? (attk + (size_t)k * 512 + c)
                                 : (reck + (size_t)k * U3_ + (c - 512));
    float4 a = reinterpret_cast<const float4*>(src)[0];
    float4 b = reinterpret_cast<const float4*>(src)[1];
    __half2 h[4];
    h[0] = __floats2half2_rn(a.x, a.y);
    h[1] = __floats2half2_rn(a.z, a.w);
    h[2] = __floats2half2_rn(b.x, b.y);
    h[3] = __floats2half2_rn(b.z, b.w);
    reinterpret_cast<uint4*>(g_Wh16)[i8] = *reinterpret_cast<uint4*>(h);
}

// biases + h init + barrier reset
__global__ void build_misc(const float* __restrict__ bimg,
                           const float* __restrict__ attb, const float* __restrict__ recb) {
    int i = blockIdx.x * blockDim.x + threadIdx.x;
    if (i == 0) g_barcnt = 0;
    if (i < NF_) g_bias2048[i] = (i < 512) ? bimg[i] : 0.f;
    if (i < HN_) g_hbias[i]    = (i < 512) ? attb[i] : recb[i - 512];
    if (i < B_ * U_) { g_h[i] = 0.f; g_h16[i] = __float2half(0.f); }
}

// ---------------- cp.async double-buffered WMMA GEMM (BK=64, profiled) -----
template<int BM, int BN, int BK, int WM, int WN, bool OUT_HALF>
__global__ __launch_bounds__(256, 2)
void gemm_pipe(const __half* __restrict__ A, const __half* __restrict__ Bm,
               const float* __restrict__ bias, float* __restrict__ Cf,
               __half* __restrict__ Ch, int M, int N, int K)
{
    constexpr int WARPS_M = BM / WM, WARPS_N = BN / WN;
    static_assert(WARPS_M * WARPS_N == 8, "8 warps");
    constexpr int FM = WM / 16, FN = WN / 16;
    constexpr int ASTR = BK + 8, BSTR = BN + 8;
    constexpr int ABYTES = BM * ASTR * 2, BBYTES = BK * BSTR * 2;
    extern __shared__ __align__(16) char smem[];

    const int tid = threadIdx.x, lane = tid & 31, wid = tid >> 5;
    const int wm = wid / WARPS_N, wn = wid % WARPS_N;
    const int m0 = blockIdx.x * BM, n0 = blockIdx.y * BN;

    wmma::fragment<wmma::accumulator, 16, 16, 16, float> acc[FM][FN];

    if (bias) {
        float* biasT = reinterpret_cast<float*>(smem);   // [16][BN]
        for (int idx = tid; idx < 16 * BN; idx += 256) biasT[idx] = bias[n0 + (idx % BN)];
        __syncthreads();
        #pragma unroll
        for (int i = 0; i < FM; i++)
            #pragma unroll
            for (int j = 0; j < FN; j++)
                wmma::load_matrix_sync(acc[i][j], biasT + wn * WN + j * 16, BN,
                                       wmma::mem_row_major);
        __syncthreads();
    } else {
        #pragma unroll
        for (int i = 0; i < FM; i++)
            #pragma unroll
            for (int j = 0; j < FN; j++) wmma::fill_fragment(acc[i][j], 0.f);
    }

    auto As = [&](int s) { return reinterpret_cast<__half*>(smem + s * ABYTES); };
    auto Bs = [&](int s) { return reinterpret_cast<__half*>(smem + 2 * ABYTES + s * BBYTES); };

    auto load_tiles = [&](int s, int k0) {
        __half* a = As(s);
        constexpr int AV = BM * BK / 8;
        #pragma unroll
        for (int v = tid; v < AV; v += 256) {
            int r = v / (BK / 8), c = (v % (BK / 8)) * 8;
            cp_async16(a + r * ASTR + c, A + (size_t)(m0 + r) * K + k0 + c);
        }
        __half* b = Bs(s);
        constexpr int BV = BK * BN / 8;
        #pragma unroll
        for (int v = tid; v < BV; v += 256) {
            int r = v / (BN / 8), c = (v % (BN / 8)) * 8;
            cp_async16(b + r * BSTR + c, Bm + (size_t)(k0 + r) * N + n0 + c);
        }
    };

    const int KT = K / BK;
    load_tiles(0, 0);
    cp_commit();

    for (int kt = 0; kt < KT; kt++) {
        const int cur = kt & 1;
        cp_wait0();
        __syncthreads();
        if (kt + 1 < KT) { load_tiles(cur ^ 1, (kt + 1) * BK); cp_commit(); }

        const __half* a = As(cur);
        const __half* b = Bs(cur);
        #pragma unroll
        for (int kk = 0; kk < BK / 16; kk++) {
            wmma::fragment<wmma::matrix_a, 16, 16, 16, __half, wmma::row_major> af[FM];
            wmma::fragment<wmma::matrix_b, 16, 16, 16, __half, wmma::row_major> bf[FN];
            #pragma unroll
            for (int i = 0; i < FM; i++)
                wmma::load_matrix_sync(af[i], a + (wm * WM + i * 16) * ASTR + kk * 16, ASTR);
            #pragma unroll
            for (int j = 0; j < FN; j++)
                wmma::load_matrix_sync(bf[j], b + (kk * 16) * BSTR + wn * WN + j * 16, BSTR);
            #pragma unroll
            for (int i = 0; i < FM; i++)
                #pragma unroll
                for (int j = 0; j < FN; j++)
                    wmma::mma_sync(acc[i][j], af[i], bf[j], acc[i][j]);
        }
        __syncthreads();
    }

    if (OUT_HALF) {
        float* stageW = reinterpret_cast<float*>(smem) + wid * 16 * 20;   // [16][20]
        const int r = lane >> 1, c0 = (lane & 1) * 8;
        #pragma unroll
        for (int i = 0; i < FM; i++)
            #pragma unroll
            for (int j = 0; j < FN; j++) {
                wmma::store_matrix_sync(stageW, acc[i][j], 20, wmma::mem_row_major);
                __syncwarp();
                const float* sp = stageW + r * 20 + c0;
                __half2 h[4];
                h[0] = __floats2half2_rn(sp[0], sp[1]);
                h[1] = __floats2half2_rn(sp[2], sp[3]);
                h[2] = __floats2half2_rn(sp[4], sp[5]);
                h[3] = __floats2half2_rn(sp[6], sp[7]);
                size_t g = (size_t)(m0 + wm * WM + i * 16 + r) * N
                         + n0 + wn * WN + j * 16 + c0;
                *reinterpret_cast<uint4*>(Ch + g) = *reinterpret_cast<uint4*>(h);
                __syncwarp();
            }
    } else {
        #pragma unroll
        for (int i = 0; i < FM; i++)
            #pragma unroll
            for (int j = 0; j < FN; j++)
                wmma::store_matrix_sync(
                    Cf + (size_t)(m0 + wm * WM + i * 16) * N + n0 + wn * WN + j * 16,
                    acc[i][j], N, wmma::mem_row_major);
    }
}

// ---------------- persistent fused step loop ----------------
// 128 CTAs x 512 threads, 1 CTA/SM. Phase G: 64x64 hmi tile per CTA.
// Phase S: 2 batches per CTA (thread halves); all hot loads are 16B-wide.
#define G2_STR (64 + 8)
#define G2_ABYTES (64 * G2_STR * 2)
#define G2_BBYTES (64 * G2_STR * 2)

struct __align__(16) PersistSmem {
    __half2 svh[A_ / 2];       // att_v as half2 (1 KB)
    float   sbias[16 * 64];    // bias broadcast tile for G (4 KB)
    union {
        char  gbuf[2 * (G2_ABYTES + G2_BBYTES)];               // 36.9 KB
        struct {
            __half2 hp2[2][A_ / 2];    // 2 KB
            float   sc[2][L_];         // 512 B
            float   att[2][L_];        // 512 B
            float   ctx[2][U3_];       // 12 KB
        } s;
    } u;
};

__global__ __launch_bounds__(512, 1)
void persist_loop(const float* __restrict__ v, float* __restrict__ out)
{
    __shared__ PersistSmem sm;
    const int tid = threadIdx.x, lane = tid & 31, wid = tid >> 5;
    const int cta = blockIdx.x;                  // 0..127

    // Phase G tile coords: 4 row blocks x 32 col blocks
    const int gm0 = (cta >> 5) * 64;
    const int gn0 = (cta & 31) * 64;
    const int wm = wid >> 2, wn = wid & 3;       // 16 warps -> 4x4 of 16x16

    // Phase S thread mapping: two batches per CTA
    const int half = tid >> 8;                   // 0 or 1
    const int t256 = tid & 255;
    const int wid8 = t256 >> 5;                  // 0..7 within half

    for (int j = tid; j < A_ / 2; j += 512)
        sm.svh[j] = __floats2half2_rn(v[2 * j], v[2 * j + 1]);
    for (int j = tid; j < 16 * 64; j += 512) sm.sbias[j] = g_hbias[gn0 + (j & 63)];
    __syncthreads();

    unsigned nbar = 0;

    for (int t = 0; t < T_; t++) {
        // ---------------- Phase G: hmi = h16 @ Wh16 + hbias ----------------
        {
            wmma::fragment<wmma::accumulator, 16, 16, 16, float> acc;
            wmma::load_matrix_sync(acc, sm.sbias + wn * 16, 64, wmma::mem_row_major);

            auto As = [&](int s) { return reinterpret_cast<__half*>(sm.u.gbuf + s * (G2_ABYTES + G2_BBYTES)); };
            auto Bs = [&](int s) { return reinterpret_cast<__half*>(sm.u.gbuf + s * (G2_ABYTES + G2_BBYTES) + G2_ABYTES); };
            auto load_tiles = [&](int s, int k0) {
                __half* a = As(s);
                {   int r = tid >> 3, c = (tid & 7) * 8;
                    cp_async16(a + r * G2_STR + c, g_h16 + (size_t)(gm0 + r) * U_ + k0 + c); }
                __half* b = Bs(s);
                {   int r = tid >> 3, c = (tid & 7) * 8;
                    cp_async16(b + r * G2_STR + c, g_Wh16 + (size_t)(k0 + r) * HN_ + gn0 + c); }
            };

            load_tiles(0, 0);
            cp_commit();
            #pragma unroll
            for (int kt = 0; kt < 8; kt++) {          // K=512, BK=64
                cp_wait0();
                __syncthreads();
                if (kt + 1 < 8) { load_tiles((kt + 1) & 1, (kt + 1) * 64); cp_commit(); }
                const __half* a = As(kt & 1);
                const __half* b = Bs(kt & 1);
                #pragma unroll
                for (int kk = 0; kk < 4; kk++) {
                    wmma::fragment<wmma::matrix_a, 16, 16, 16, __half, wmma::row_major> af;
                    wmma::fragment<wmma::matrix_b, 16, 16, 16, __half, wmma::row_major> bf;
                    wmma::load_matrix_sync(af, a + (wm * 16) * G2_STR + kk * 16, G2_STR);
                    wmma::load_matrix_sync(bf, b + (kk * 16) * G2_STR + wn * 16, G2_STR);
                    wmma::mma_sync(acc, af, bf, acc);
                }
                __syncthreads();
            }
            wmma::store_matrix_sync(g_hmi + (size_t)(gm0 + wm * 16) * HN_ + gn0 + wn * 16,
                                    acc, HN_, wmma::mem_row_major);
        }
        grid_sync(++nbar * 128u);

        // ---------------- Phase S: attention + softmax + ctx + gates ------
        {
            const int b = cta * 2 + half;
            const float* hmi = g_hmi + b * HN_;
            // hp as packed half2 (one element per thread)
            {
                int j = t256;                        // A_/2 == 256
                float a0 = __ldcg(&hmi[2 * j]);
                float a1 = __ldcg(&hmi[2 * j + 1]);
                sm.u.s.hp2[half][j] = __floats2half2_rn(a0, a1);
            }
            __syncthreads();

            // scores: 16B-wide loads (2x LDG.128 per lane per region)
            const uint4* ip4base = reinterpret_cast<const uint4*>(
                g_imgpk + (size_t)b * L_ * NF_);     // 256 uint4 per row
            const uint4* hp4 = reinterpret_cast<const uint4*>(sm.u.s.hp2[half]);
            const uint4* sv4 = reinterpret_cast<const uint4*>(sm.svh);
            for (int l = wid8; l < L_; l += 8) {
                const uint4* ip = ip4base + (size_t)l * (NF_ / 8);
                float s = 0.f;
                #pragma unroll
                for (int q = 0; q < 2; q++) {
                    int idx = lane + q * 32;         // 0..63 (imgproj = first 64 uint4)
                    uint4 av = ip[idx];
                    uint4 hv = hp4[idx];
                    uint4 vv = sv4[idx];
                    const __half2* ah = reinterpret_cast<const __half2*>(&av);
                    const __half2* hh = reinterpret_cast<const __half2*>(&hv);
                    const __half2* vh = reinterpret_cast<const __half2*>(&vv);
                    #pragma unroll
                    for (int k = 0; k < 4; k++) {
                        __half2 t2 = tanh2_fast(__hadd2(ah[k], hh[k]));
                        float2 tf = __half22float2(t2);
                        float2 vf = __half22float2(vh[k]);
                        s += tf.x * vf.x + tf.y * vf.y;
                    }
                }
                #pragma unroll
                for (int o = 16; o; o >>= 1) s += __shfl_xor_sync(0xffffffffu, s, o);
                if (!lane) sm.u.s.sc[half][l] = s;
            }
            __syncthreads();

            if (t256 < 32) {
                float v1 = sm.u.s.sc[half][t256], v2 = sm.u.s.sc[half][t256 + 32];
                float m = fmaxf(v1, v2);
                #pragma unroll
                for (int o = 16; o; o >>= 1) m = fmaxf(m, __shfl_xor_sync(0xffffffffu, m, o));
                float e1 = expf(v1 - m), e2 = expf(v2 - m);
                float ssum = e1 + e2;
                #pragma unroll
                for (int o = 16; o; o >>= 1) ssum += __shfl_xor_sync(0xffffffffu, ssum, o);
                float inv = 1.f / ssum;
                sm.u.s.att[half][t256] = e1 * inv;
                sm.u.s.att[half][t256 + 32] = e2 * inv;
            }
            __syncthreads();

            // ctx: 192 threads x uint4 (8 contiguous cols), staged to smem
            if (t256 < 192) {
                float acc8[8] = {0.f, 0.f, 0.f, 0.f, 0.f, 0.f, 0.f, 0.f};
                const float* att = sm.u.s.att[half];
                const uint4* kb = ip4base + 64 + t256;     // cols [512,2048): uint4 64..255
                for (int l = 0; l < L_; l += 2) {
                    float w0 = att[l], w1 = att[l + 1];
                    uint4 a0 = kb[(size_t)l * 256];
                    uint4 a1 = kb[(size_t)(l + 1) * 256];
                    const __half2* f0 = reinterpret_cast<const __half2*>(&a0);
                    const __half2* f1 = reinterpret_cast<const __half2*>(&a1);
                    #pragma unroll
                    for (int k = 0; k < 4; k++) {
                        float2 x0 = __half22float2(f0[k]);
                        float2 x1 = __half22float2(f1[k]);
                        acc8[2 * k]     += w0 * x0.x + w1 * x1.x;
                        acc8[2 * k + 1] += w0 * x0.y + w1 * x1.y;
                    }
                }
                #pragma unroll
                for (int k = 0; k < 8; k++)
                    sm.u.s.ctx[half][t256 * 8 + k] = acc8[k];
            }
            __syncthreads();

            // gates: float2-paired loads/stores, ctx from smem
            const float* ctx = sm.u.s.ctx[half];
            const float2* mxt2 = reinterpret_cast<const float2*>(
                g_mxtext + ((size_t)b * T_ + t) * U3_);
            const float2* hmi2 = reinterpret_cast<const float2*>(hmi);
            float2* h2 = reinterpret_cast<float2*>(g_h + b * U_);
            __half2* h16v = reinterpret_cast<__half2*>(g_h16 + b * U_);
            float2* out2 = reinterpret_cast<float2*>(
                out + ((size_t)b * T_ + t) * U_);

            float2 mz = mxt2[t256], mr = mxt2[256 + t256], mh = mxt2[512 + t256];
            float2 rz2 = __ldcg(&hmi2[256 + t256]);
            float2 rr2 = __ldcg(&hmi2[512 + t256]);
            float2 rh2 = __ldcg(&hmi2[768 + t256]);
            float2 ho2 = h2[t256];
            int u0 = 2 * t256;
            float hn01[2];
            #pragma unroll
            for (int p = 0; p < 2; p++) {
                int u = u0 + p;
                float xz = (p ? mz.y : mz.x) + ctx[u];
                float xr = (p ? mr.y : mr.x) + ctx[512 + u];
                float xh = (p ? mh.y : mh.x) + ctx[1024 + u];
                float rz = p ? rz2.y : rz2.x;
                float rr = p ? rr2.y : rr2.x;
                float rh = p ? rh2.y : rh2.x;
                float z  = 1.f / (1.f + expf(-(xz + rz)));
                float r  = 1.f / (1.f + expf(-(xr + rr)));
                float hh = tanhf(xh + r * rh);
                float ho = p ? ho2.y : ho2.x;
                hn01[p] = z * ho + (1.f - z) * hh;
            }
            float2 hn2 = make_float2(hn01[0], hn01[1]);
            out2[t256] = hn2;
            h2[t256] = hn2;
            h16v[t256] = __floats2half2_rn(hn01[0], hn01[1]);
        }
        if (t + 1 < T_) grid_sync(++nbar * 128u);
    }
}

// ---------------- host launcher ----------------
extern "C" void kernel_launch(void* const* d_in, const int* in_sizes, int n_in,
                              void* d_out, int out_size)
{
    const float* img    = (const float*)d_in[0];
    const float* text   = (const float*)d_in[1];
    const float* kernel = (const float*)d_in[2];
    const float* ibias  = (const float*)d_in[3];
    const float* reck   = (const float*)d_in[4];
    const float* rbias  = (const float*)d_in[5];
    const float* wimg   = (const float*)d_in[6];
    const float* bimg   = (const float*)d_in[7];
    const float* attk   = (const float*)d_in[8];
    const float* attb   = (const float*)d_in[9];
    const float* vvec   = (const float*)d_in[10];
    float* out = (float*)d_out;

    void *pImg16, *pText16, *pWbig, *pWtext, *pBias2048, *pImgpk, *pMxtext;
    cudaGetSymbolAddress(&pImg16,   g_img16);
    cudaGetSymbolAddress(&pText16,  g_text16);
    cudaGetSymbolAddress(&pWbig,    g_Wbig);
    cudaGetSymbolAddress(&pWtext,   g_Wtext);
    cudaGetSymbolAddress(&pBias2048,g_bias2048);
    cudaGetSymbolAddress(&pImgpk,   g_imgpk);
    cudaGetSymbolAddress(&pMxtext,  g_mxtext);

    constexpr int GEMM_SMEM = 2 * (128 * (64 + 8) * 2 + 64 * (128 + 8) * 2);  // 71680
    cudaFuncSetAttribute(gemm_pipe<128, 128, 64, 64, 32, true>,
                         cudaFuncAttributeMaxDynamicSharedMemorySize, GEMM_SMEM);
    cudaFuncSetAttribute(gemm_pipe<128, 128, 64, 64, 32, false>,
                         cudaFuncAttributeMaxDynamicSharedMemorySize, GEMM_SMEM);

    // ---- launch order: big GEMM stays launch #3 (ncu lands there) ----------
    size_t n_img8 = (size_t)B_ * L_ * DI_ / 8;
    cvt_f32_f16_v8<<<(unsigned)((n_img8 + 255) / 256), 256>>>(img, (__half*)pImg16, n_img8);   // 0
    copy_weights<<<dim3(512, 3), 256>>>(wimg, kernel);                                         // 1
    build_misc<<<(B_ * U_ + 255) / 256, 256>>>(bimg, attb, rbias);                             // 2

    // fused: [imgproj | img_k] = img16 @ Wbig + bias2048 -> fp16 [16384, 2048]
    gemm_pipe<128, 128, 64, 64, 32, true>
        <<<dim3(16384 / 128, NF_ / 128), 256, GEMM_SMEM>>>(                                    // 3
        (const __half*)pImg16, (const __half*)pWbig, (const float*)pBias2048,
        nullptr, (__half*)pImgpk, 16384, NF_, DI_);

    size_t n_txt8 = (size_t)B_ * T_ * DT_ / 8;
    cvt_f32_f16_v8<<<(unsigned)((n_txt8 + 255) / 256), 256>>>(text, (__half*)pText16, n_txt8); // 4
    build_Wh_v8<<<(U_ * HN_ / 8) / 256, 256>>>(attk, reck);                                    // 5

    // mx_text = text16 @ Wtext + ibias -> fp32 [8192, 1536]
    gemm_pipe<128, 128, 64, 64, 32, false>
        <<<dim3(8192 / 128, U3_ / 128), 256, GEMM_SMEM>>>(                                     // 6
        (const __half*)pText16, (const __half*)pWtext, ibias,
        (float*)pMxtext, nullptr, 8192, U3_, DT_);

    // persistent GRU loop: 128 CTAs x 512 threads, 1 CTA/SM
    persist_loop<<<128, 512>>>(vvec, out);                                                     // 7
}